// round 1
// baseline (speedup 1.0000x reference)
#include <cuda_runtime.h>
#include <math.h>
#include <float.h>

// ----------------------------------------------------------------------------
// MoleculeGCN forward, restructured:
//  - EdgeConv: msg = [x_i, x_j-x_i]@Wb = x_i@(W1-W2) + x_j@W2  -> per-node GEMMs
//    segment_max(P[dst]+Q[src]) = P[dst] + segmax_{in}(Q[src])
//  - Step-1 h_b has only 20 distinct rows (bond vocab) -> 20-row P/Q tables
//  - h_b rows e>=N (and deg-0 rows) are the constant softplus(0) vector ->
//    h_b@W_edge is a single precomputed constant vector for those edges
//  - All scatters replaced by dst-CSR gather loops (no float atomics)
// ----------------------------------------------------------------------------

#define NMAX 100032   // 100000 padded to multiple of 64 (GEMM tile M)
#define EMAX 400000
#define GMAX 4096
#define C0 0.69314718055994531f   // softplus(0) = ln 2

// scratch (device globals: allowed scratch mechanism)
__device__ float g_ha[(size_t)NMAX * 128];
__device__ float g_hb[(size_t)NMAX * 128];
__device__ float g_X [(size_t)NMAX * 128];
__device__ float g_Y [(size_t)NMAX * 128];
__device__ int   g_deg[NMAX];
__device__ int   g_rowptr[NMAX + 1];
__device__ int   g_fill[NMAX];
__device__ int   g_bsum[1024];
__device__ int2  g_csr[EMAX];
__device__ float g_WP[128 * 128];
__device__ float g_P20[20 * 128];
__device__ float g_Q20[20 * 128];
__device__ float g_Cc[128];
__device__ float g_pooled[GMAX * 128];

__device__ __forceinline__ float sp(float x) {
    // logaddexp(x, 0) = max(x,0) + log1p(exp(-|x|))  (matches jax.nn.softplus)
    return fmaxf(x, 0.f) + log1pf(__expf(-fabsf(x)));
}

__device__ __forceinline__ float* selbuf(int s) {
    return s == 0 ? g_ha : s == 1 ? g_hb : s == 2 ? g_X : g_Y;
}

// ---------------------------------------------------------------- CSR build
__global__ void k_zero_deg(int N_) {
    int i = blockIdx.x * blockDim.x + threadIdx.x;
    if (i < N_) g_deg[i] = 0;
}
__global__ void k_hist(const int* __restrict__ dst, int E_) {
    int e = blockIdx.x * blockDim.x + threadIdx.x;
    if (e < E_) atomicAdd(&g_deg[dst[e]], 1);
}
__global__ __launch_bounds__(1024) void k_scan1(int N_) {
    int t = threadIdx.x, b = blockIdx.x, i = b * 1024 + t;
    int v = (i < N_) ? g_deg[i] : 0;
    int lane = t & 31, wid = t >> 5;
    int incl = v;
#pragma unroll
    for (int o = 1; o < 32; o <<= 1) {
        int u = __shfl_up_sync(0xffffffffu, incl, o);
        if (lane >= o) incl += u;
    }
    __shared__ int ws[32];
    if (lane == 31) ws[wid] = incl;
    __syncthreads();
    if (wid == 0) {
        int x = ws[lane];
#pragma unroll
        for (int o = 1; o < 32; o <<= 1) {
            int u = __shfl_up_sync(0xffffffffu, x, o);
            if (lane >= o) x += u;
        }
        ws[lane] = x;
    }
    __syncthreads();
    int off = wid ? ws[wid - 1] : 0;
    if (i < N_) g_rowptr[i] = off + incl - v;
    if (t == 1023) g_bsum[b] = off + incl;
}
__global__ __launch_bounds__(1024) void k_scan2(int nb) {
    int t = threadIdx.x;
    int v = (t < nb) ? g_bsum[t] : 0;
    int lane = t & 31, wid = t >> 5;
    int incl = v;
#pragma unroll
    for (int o = 1; o < 32; o <<= 1) {
        int u = __shfl_up_sync(0xffffffffu, incl, o);
        if (lane >= o) incl += u;
    }
    __shared__ int ws[32];
    if (lane == 31) ws[wid] = incl;
    __syncthreads();
    if (wid == 0) {
        int x = ws[lane];
#pragma unroll
        for (int o = 1; o < 32; o <<= 1) {
            int u = __shfl_up_sync(0xffffffffu, x, o);
            if (lane >= o) x += u;
        }
        ws[lane] = x;
    }
    __syncthreads();
    int off = wid ? ws[wid - 1] : 0;
    if (t < nb) g_bsum[t] = off + incl - v;
}
__global__ void k_scan3(int N_, int E_) {
    int i = blockIdx.x * blockDim.x + threadIdx.x;
    if (i < N_) {
        int r = g_rowptr[i] + g_bsum[i >> 10];
        g_rowptr[i] = r;
        g_fill[i] = r;
    }
    if (i == 0) g_rowptr[N_] = E_;
}
__global__ void k_fill_csr(const int* __restrict__ src, const int* __restrict__ dst, int E_) {
    int e = blockIdx.x * blockDim.x + threadIdx.x;
    if (e < E_) {
        int p = atomicAdd(&g_fill[dst[e]], 1);
        g_csr[p] = make_int2(src[e], e);
    }
}

// ---------------------------------------------------------------- init / prep
__global__ void k_init_ha(const int* __restrict__ xids, const float* __restrict__ ea, int N_) {
    int i = blockIdx.x * blockDim.x + threadIdx.x;
    if (i < N_ * 128) {
        int n = i >> 7, c = i & 127;
        g_ha[i] = sp(ea[xids[n] * 128 + c]);
    }
}
__global__ void k_prep_wp(const float* __restrict__ Wb) {
    int i = blockIdx.x * blockDim.x + threadIdx.x;
    if (i < 16384) g_WP[i] = Wb[i] - Wb[i + 16384];
}
__global__ void k_prep_pq20(const float* __restrict__ eb, const float* __restrict__ Wb,
                            const float* __restrict__ bb) {
    __shared__ float h[128];
    int k = blockIdx.x, j = threadIdx.x;
    h[j] = sp(eb[k * 128 + j]);
    __syncthreads();
    float p = bb[j], q = 0.f;
    for (int kk = 0; kk < 128; kk++) {
        float hv = h[kk];
        p = fmaf(hv, g_WP[kk * 128 + j], p);
        q = fmaf(hv, Wb[(128 + kk) * 128 + j], q);
    }
    g_P20[k * 128 + j] = p;
    g_Q20[k * 128 + j] = q;
}
__global__ void k_prep_c(const float* __restrict__ We, const float* __restrict__ be) {
    int j = threadIdx.x;
    float s = be[j];
    for (int k = 0; k < 128; k++) s = fmaf(C0, We[k * 128 + j], s);
    g_Cc[j] = s;
}

// ---------------------------------------------------------------- SGEMM [*,128]@[128,128]
__global__ __launch_bounds__(256) void sgemm_n128(int in_sel, const float* __restrict__ Wext,
                                                  const float* __restrict__ bias, int out_sel,
                                                  int use_wp) {
    __shared__ float As[16][68];
    __shared__ float Bs[16][128];
    const float* A = selbuf(in_sel);
    float* C = selbuf(out_sel);
    const float* W = use_wp ? g_WP : Wext;
    const int tid = threadIdx.x;
    const int tx = tid & 15;
    const int ty = tid >> 4;
    const int m0 = blockIdx.x * 64;
    const int arow = tid >> 2;
    const int akq = (tid & 3) * 4;
    float acc[4][8];
#pragma unroll
    for (int i = 0; i < 4; i++)
#pragma unroll
        for (int j = 0; j < 8; j++) acc[i][j] = 0.f;

    for (int k0 = 0; k0 < 128; k0 += 16) {
        float4 av = *(const float4*)(A + (size_t)(m0 + arow) * 128 + k0 + akq);
        As[akq + 0][arow] = av.x;
        As[akq + 1][arow] = av.y;
        As[akq + 2][arow] = av.z;
        As[akq + 3][arow] = av.w;
#pragma unroll
        for (int r = 0; r < 2; r++) {
            int f = tid + r * 256;
            int bk = f >> 5, bj = (f & 31) * 4;
            *(float4*)&Bs[bk][bj] = *(const float4*)(W + (size_t)(k0 + bk) * 128 + bj);
        }
        __syncthreads();
#pragma unroll
        for (int kk = 0; kk < 16; kk++) {
            float4 a = *(const float4*)&As[kk][ty * 4];
            float4 b0 = *(const float4*)&Bs[kk][tx * 8];
            float4 b1 = *(const float4*)&Bs[kk][tx * 8 + 4];
            float av4[4] = {a.x, a.y, a.z, a.w};
            float bv[8] = {b0.x, b0.y, b0.z, b0.w, b1.x, b1.y, b1.z, b1.w};
#pragma unroll
            for (int i = 0; i < 4; i++)
#pragma unroll
                for (int j = 0; j < 8; j++) acc[i][j] = fmaf(av4[i], bv[j], acc[i][j]);
        }
        __syncthreads();
    }
    float bsv[8];
    if (bias) {
        float4 q0 = *(const float4*)(bias + tx * 8);
        float4 q1 = *(const float4*)(bias + tx * 8 + 4);
        bsv[0] = q0.x; bsv[1] = q0.y; bsv[2] = q0.z; bsv[3] = q0.w;
        bsv[4] = q1.x; bsv[5] = q1.y; bsv[6] = q1.z; bsv[7] = q1.w;
    } else {
#pragma unroll
        for (int j = 0; j < 8; j++) bsv[j] = 0.f;
    }
#pragma unroll
    for (int i = 0; i < 4; i++) {
        int row = m0 + ty * 4 + i;
        float4 o0 = make_float4(acc[i][0] + bsv[0], acc[i][1] + bsv[1],
                                acc[i][2] + bsv[2], acc[i][3] + bsv[3]);
        float4 o1 = make_float4(acc[i][4] + bsv[4], acc[i][5] + bsv[5],
                                acc[i][6] + bsv[6], acc[i][7] + bsv[7]);
        *(float4*)(C + (size_t)row * 128 + tx * 8) = o0;
        *(float4*)(C + (size_t)row * 128 + tx * 8 + 4) = o1;
    }
}

// ---------------------------------------------------------------- aggregations
// EdgeConv: h_b[d] = softplus( deg>0 ? P[d] + max_in Q[src] : 0 ). Warp per node.
__global__ void edgeconv_agg(int step1, const int* __restrict__ remap,
                             float* __restrict__ outExt, int N_) {
    int w = (blockIdx.x * blockDim.x + threadIdx.x) >> 5;
    if (w >= N_) return;
    int lane = threadIdx.x & 31;
    const float* P = step1 ? g_P20 : g_X;
    const float* Q = step1 ? g_Q20 : g_Y;
    int lo = g_rowptr[w], hi = g_rowptr[w + 1];
    float4 r;
    if (lo == hi) {
        r = make_float4(C0, C0, C0, C0);
    } else {
        float4 m = make_float4(-FLT_MAX, -FLT_MAX, -FLT_MAX, -FLT_MAX);
        for (int i = lo; i < hi; i++) {
            int s = g_csr[i].x;
            int qs = step1 ? remap[s] : s;
            float4 q = *(const float4*)(Q + (size_t)qs * 128 + lane * 4);
            m.x = fmaxf(m.x, q.x); m.y = fmaxf(m.y, q.y);
            m.z = fmaxf(m.z, q.z); m.w = fmaxf(m.w, q.w);
        }
        int pd = step1 ? remap[w] : w;
        float4 p = *(const float4*)(P + (size_t)pd * 128 + lane * 4);
        r = make_float4(sp(p.x + m.x), sp(p.y + m.y), sp(p.z + m.z), sp(p.w + m.w));
    }
    *(float4*)(g_hb + (size_t)w * 128 + lane * 4) = r;
    if (outExt) *(float4*)(outExt + (size_t)w * 128 + lane * 4) = r;
}

// GeneralConv: h_a[d] = softplus( sum_in (A[src] + (e<N ? Bv[e] : Cc)) + h_a[d] )
__global__ void genconv_agg(float* __restrict__ outExt, int N_) {
    int w = (blockIdx.x * blockDim.x + threadIdx.x) >> 5;
    if (w >= N_) return;
    int lane = threadIdx.x & 31;
    int lo = g_rowptr[w], hi = g_rowptr[w + 1];
    float4 acc = make_float4(0.f, 0.f, 0.f, 0.f);
    for (int i = lo; i < hi; i++) {
        int2 se = g_csr[i];
        float4 a = *(const float4*)(g_X + (size_t)se.x * 128 + lane * 4);
        const float* Bp = (se.y < N_) ? (g_Y + (size_t)se.y * 128) : g_Cc;
        float4 b = *(const float4*)(Bp + lane * 4);
        acc.x += a.x + b.x; acc.y += a.y + b.y;
        acc.z += a.z + b.z; acc.w += a.w + b.w;
    }
    float4 h = *(const float4*)(g_ha + (size_t)w * 128 + lane * 4);
    float4 r = make_float4(sp(acc.x + h.x), sp(acc.y + h.y), sp(acc.z + h.z), sp(acc.w + h.w));
    *(float4*)(g_ha + (size_t)w * 128 + lane * 4) = r;
    if (outExt) *(float4*)(outExt + (size_t)w * 128 + lane * 4) = r;
}

__global__ void k_fill_tail(float* __restrict__ dst4, size_t count4) {
    size_t i = (size_t)blockIdx.x * blockDim.x + threadIdx.x;
    if (i < count4) ((float4*)dst4)[i] = make_float4(C0, C0, C0, C0);
}

// ---------------------------------------------------------------- pool + MLP
__device__ __forceinline__ int lbound(const int* a, int n, int key) {
    int lo = 0, hi = n;
    while (lo < hi) {
        int mid = (lo + hi) >> 1;
        if (a[mid] < key) lo = mid + 1; else hi = mid;
    }
    return lo;
}
__global__ void k_pool(const int* __restrict__ batch, int N_) {
    int g = blockIdx.x, j = threadIdx.x;
    int lo = lbound(batch, N_, g), hi = lbound(batch, N_, g + 1);
    float acc = 0.f;
    for (int n = lo; n < hi; n++) acc += g_ha[(size_t)n * 128 + j];
    g_pooled[g * 128 + j] = acc;
}
__global__ void k_readout(const float* __restrict__ Wr1, const float* __restrict__ br1,
                          const float* __restrict__ Wr2, const float* __restrict__ br2,
                          const float* __restrict__ Wr3, const float* __restrict__ br3,
                          float* __restrict__ out) {
    int g = blockIdx.x, j = threadIdx.x;  // 64 threads
    __shared__ float p[128];
    __shared__ float h[64];
    __shared__ float part[2];
    p[j] = g_pooled[g * 128 + j];
    p[j + 64] = g_pooled[g * 128 + 64 + j];
    __syncthreads();
    float s = br1[j];
    for (int k = 0; k < 128; k++) s = fmaf(p[k], Wr1[k * 64 + j], s);
    h[j] = sp(s);
    __syncthreads();
    float s2 = br2[j];
    for (int k = 0; k < 64; k++) s2 = fmaf(h[k], Wr2[k * 64 + j], s2);
    float v = sp(s2) * Wr3[j];
#pragma unroll
    for (int o = 16; o; o >>= 1) v += __shfl_down_sync(0xffffffffu, v, o);
    if ((j & 31) == 0) part[j >> 5] = v;
    __syncthreads();
    if (j == 0) out[g] = part[0] + part[1] + br3[0];
}

// ---------------------------------------------------------------- launch
extern "C" void kernel_launch(void* const* d_in, const int* in_sizes, int n_in,
                              void* d_out, int out_size) {
    const int* x_ids = (const int*)d_in[0];
    const int* eaid  = (const int*)d_in[1];
    const int* eidx  = (const int*)d_in[2];
    const int* batch = (const int*)d_in[3];
    const float* emb_atom = (const float*)d_in[4];
    const float* emb_bond = (const float*)d_in[5];
    const float* Wb  = (const float*)d_in[6];
    const float* bb  = (const float*)d_in[7];
    const float* Wm  = (const float*)d_in[8];
    const float* bm  = (const float*)d_in[9];
    const float* We  = (const float*)d_in[10];
    const float* be  = (const float*)d_in[11];
    const float* Wr1 = (const float*)d_in[12];
    const float* br1 = (const float*)d_in[13];
    const float* Wr2 = (const float*)d_in[14];
    const float* br2 = (const float*)d_in[15];
    const float* Wr3 = (const float*)d_in[16];
    const float* br3 = (const float*)d_in[17];
    const int N = in_sizes[0];
    const int E = in_sizes[1];
    const int G = out_size - 128 * (N + E);   // 4096
    const int* srcp = eidx;
    const int* dstp = eidx + E;
    float* out = (float*)d_out;
    float* out_ha = out + G;
    float* out_hb = out_ha + (size_t)N * 128;

    const int nb = (N + 1023) / 1024;
    const int gemm_grid = (N + 63) / 64;
    const int agg_grid = (N + 7) / 8;

    // CSR by dst (also gives has_nb = deg>0)
    k_zero_deg<<<(N + 255) / 256, 256>>>(N);
    k_hist<<<(E + 255) / 256, 256>>>(dstp, E);
    k_scan1<<<nb, 1024>>>(N);
    k_scan2<<<1, 1024>>>(nb);
    k_scan3<<<(N + 255) / 256, 256>>>(N, E);
    k_fill_csr<<<(E + 255) / 256, 256>>>(srcp, dstp, E);

    // init + prep
    k_init_ha<<<(N * 128 + 255) / 256, 256>>>(x_ids, emb_atom, N);
    k_prep_wp<<<64, 256>>>(Wb);
    k_prep_pq20<<<20, 128>>>(emb_bond, Wb, bb);
    k_prep_c<<<1, 128>>>(We, be);

    // ---- step 1 ----
    edgeconv_agg<<<agg_grid, 256>>>(1, eaid, nullptr, N);           // h_b1 (20-row P/Q tables)
    sgemm_n128<<<gemm_grid, 256>>>(0, Wm, bm, 2, 0);                // A1  = h_a0@Wm+bm -> X
    sgemm_n128<<<gemm_grid, 256>>>(1, We, be, 3, 0);                // Bv1 = h_b1@We+be -> Y
    genconv_agg<<<agg_grid, 256>>>(nullptr, N);                     // h_a1 (in place)

    // ---- step 2 ----
    sgemm_n128<<<gemm_grid, 256>>>(1, nullptr, bb, 2, 1);           // P2 = h_b1@(W1-W2)+bb -> X
    sgemm_n128<<<gemm_grid, 256>>>(1, Wb + 128 * 128, nullptr, 3, 0); // Q2 = h_b1@W2 -> Y
    edgeconv_agg<<<agg_grid, 256>>>(0, nullptr, out_hb, N);         // h_b2 (+ write output rows <N)
    {
        size_t count4 = ((size_t)(E - N) * 128) / 4;                // output rows >= N are softplus(0)
        k_fill_tail<<<(unsigned)((count4 + 255) / 256), 256>>>(out_hb + (size_t)N * 128, count4);
    }
    sgemm_n128<<<gemm_grid, 256>>>(0, Wm, bm, 2, 0);                // A2  = h_a1@Wm+bm -> X
    sgemm_n128<<<gemm_grid, 256>>>(1, We, be, 3, 0);                // Bv2 = h_b2@We+be -> Y
    genconv_agg<<<agg_grid, 256>>>(out_ha, N);                      // h_a2 (+ write output)

    // ---- pool + readout ----
    k_pool<<<G, 128>>>(batch, N);
    k_readout<<<G, 64>>>(Wr1, br1, Wr2, br2, Wr3, br3, out);
}

// round 5
// speedup vs baseline: 1.4256x; 1.4256x over previous
#include <cuda_runtime.h>
#include <math.h>
#include <float.h>
#include <stdint.h>

// ----------------------------------------------------------------------------
// MoleculeGCN forward.
//  - EdgeConv: msg = [x_i, x_j-x_i]@Wb = x_i@(W1-W2) + x_j@W2 -> per-node GEMMs
//  - Step-1 h_b: only 20 distinct rows -> 20-row P/Q tables
//  - h_b rows e>=N / deg-0 rows are constant softplus(0) -> h_b@W_edge constant
//  - dst-CSR gathers (no float atomics)
//  - GEMMs: 3xTF32 tensor-core mma (hi/lo split) -> near-fp32 accuracy
// ----------------------------------------------------------------------------

#define NMAX 100096   // multiple of 128 (GEMM tile M)
#define EMAX 400000
#define GMAX 4096
#define C0 0.69314718055994531f   // softplus(0) = ln 2

// scratch (device globals)
__device__ float g_ha[(size_t)NMAX * 128];
__device__ float g_hb[(size_t)NMAX * 128];
__device__ float g_X [(size_t)NMAX * 128];
__device__ float g_Y [(size_t)NMAX * 128];
__device__ int   g_deg[NMAX];
__device__ int   g_rowptr[NMAX + 1];
__device__ int   g_fill[NMAX];
__device__ int   g_bsum[1024];
__device__ int2  g_csr[EMAX];
__device__ float g_WP[128 * 128];
__device__ float g_P20[20 * 128];
__device__ float g_Q20[20 * 128];
__device__ float g_Cc[128];
__device__ float g_pooled[GMAX * 128];
// pre-split tf32 weights: 0=Wm 1=We 2=WP(W1-W2) 3=W2
__device__ float g_Whi[4][16384];
__device__ float g_Wlo[4][16384];

__device__ __forceinline__ float sp(float x) {
    return fmaxf(x, 0.f) + log1pf(__expf(-fabsf(x)));
}
__device__ __forceinline__ uint32_t f2tf32(float x) {
    uint32_t r;
    asm("cvt.rna.tf32.f32 %0, %1;" : "=r"(r) : "f"(x));
    return r;
}
__device__ __forceinline__ void mma_tf32(float* d, const uint32_t* a, uint32_t b0, uint32_t b1) {
    asm volatile(
        "mma.sync.aligned.m16n8k8.row.col.f32.tf32.tf32.f32 "
        "{%0,%1,%2,%3}, {%4,%5,%6,%7}, {%8,%9}, {%0,%1,%2,%3};"
        : "+f"(d[0]), "+f"(d[1]), "+f"(d[2]), "+f"(d[3])
        : "r"(a[0]), "r"(a[1]), "r"(a[2]), "r"(a[3]), "r"(b0), "r"(b1));
}

// ---------------------------------------------------------------- CSR build
__global__ void k_zero_deg(int N_) {
    int i = blockIdx.x * blockDim.x + threadIdx.x;
    if (i < N_) g_deg[i] = 0;
}
__global__ void k_hist(const int* __restrict__ dst, int E_) {
    int e = blockIdx.x * blockDim.x + threadIdx.x;
    if (e < E_) atomicAdd(&g_deg[dst[e]], 1);
}
__global__ __launch_bounds__(1024) void k_scan1(int N_) {
    int t = threadIdx.x, b = blockIdx.x, i = b * 1024 + t;
    int v = (i < N_) ? g_deg[i] : 0;
    int lane = t & 31, wid = t >> 5;
    int incl = v;
#pragma unroll
    for (int o = 1; o < 32; o <<= 1) {
        int u = __shfl_up_sync(0xffffffffu, incl, o);
        if (lane >= o) incl += u;
    }
    __shared__ int ws[32];
    if (lane == 31) ws[wid] = incl;
    __syncthreads();
    if (wid == 0) {
        int x = ws[lane];
#pragma unroll
        for (int o = 1; o < 32; o <<= 1) {
            int u = __shfl_up_sync(0xffffffffu, x, o);
            if (lane >= o) x += u;
        }
        ws[lane] = x;
    }
    __syncthreads();
    int off = wid ? ws[wid - 1] : 0;
    if (i < N_) g_rowptr[i] = off + incl - v;
    if (t == 1023) g_bsum[b] = off + incl;
}
__global__ __launch_bounds__(1024) void k_scan2(int nb) {
    int t = threadIdx.x;
    int v = (t < nb) ? g_bsum[t] : 0;
    int lane = t & 31, wid = t >> 5;
    int incl = v;
#pragma unroll
    for (int o = 1; o < 32; o <<= 1) {
        int u = __shfl_up_sync(0xffffffffu, incl, o);
        if (lane >= o) incl += u;
    }
    __shared__ int ws[32];
    if (lane == 31) ws[wid] = incl;
    __syncthreads();
    if (wid == 0) {
        int x = ws[lane];
#pragma unroll
        for (int o = 1; o < 32; o <<= 1) {
            int u = __shfl_up_sync(0xffffffffu, x, o);
            if (lane >= o) x += u;
        }
        ws[lane] = x;
    }
    __syncthreads();
    int off = wid ? ws[wid - 1] : 0;
    if (t < nb) g_bsum[t] = off + incl - v;
}
__global__ void k_scan3(int N_, int E_) {
    int i = blockIdx.x * blockDim.x + threadIdx.x;
    if (i < N_) {
        int r = g_rowptr[i] + g_bsum[i >> 10];
        g_rowptr[i] = r;
        g_fill[i] = r;
    }
    if (i == 0) g_rowptr[N_] = E_;
}
__global__ void k_fill_csr(const int* __restrict__ src, const int* __restrict__ dst, int E_) {
    int e = blockIdx.x * blockDim.x + threadIdx.x;
    if (e < E_) {
        int p = atomicAdd(&g_fill[dst[e]], 1);
        g_csr[p] = make_int2(src[e], e);
    }
}

// ---------------------------------------------------------------- init / prep
__global__ void k_init_ha(const int* __restrict__ xids, const float* __restrict__ ea, int N_) {
    int i = blockIdx.x * blockDim.x + threadIdx.x;
    if (i < N_ * 128) {
        int n = i >> 7, c = i & 127;
        g_ha[i] = sp(ea[xids[n] * 128 + c]);
    }
}
__global__ void k_prep_wp(const float* __restrict__ Wb) {
    int i = blockIdx.x * blockDim.x + threadIdx.x;
    if (i < 16384) g_WP[i] = Wb[i] - Wb[i + 16384];
}
// split fp32 weight into tf32 hi/lo
__global__ void k_split(const float* __restrict__ src, int widx) {
    int i = blockIdx.x * blockDim.x + threadIdx.x;
    if (i < 16384) {
        float v = src[i];
        float hi = __uint_as_float(f2tf32(v));
        g_Whi[widx][i] = hi;
        g_Wlo[widx][i] = __uint_as_float(f2tf32(v - hi));
    }
}
__global__ void k_split_wb(const float* __restrict__ Wb) {
    int i = blockIdx.x * blockDim.x + threadIdx.x;
    if (i < 16384) {
        float w2 = Wb[i + 16384];
        float wp = Wb[i] - w2;
        float hi = __uint_as_float(f2tf32(wp));
        g_Whi[2][i] = hi;
        g_Wlo[2][i] = __uint_as_float(f2tf32(wp - hi));
        hi = __uint_as_float(f2tf32(w2));
        g_Whi[3][i] = hi;
        g_Wlo[3][i] = __uint_as_float(f2tf32(w2 - hi));
    }
}
__global__ void k_prep_pq20(const float* __restrict__ eb, const float* __restrict__ Wb,
                            const float* __restrict__ bb) {
    __shared__ float h[128];
    int k = blockIdx.x, j = threadIdx.x;
    h[j] = sp(eb[k * 128 + j]);
    __syncthreads();
    float p = bb[j], q = 0.f;
    for (int kk = 0; kk < 128; kk++) {
        float hv = h[kk];
        p = fmaf(hv, g_WP[kk * 128 + j], p);
        q = fmaf(hv, Wb[(128 + kk) * 128 + j], q);
    }
    g_P20[k * 128 + j] = p;
    g_Q20[k * 128 + j] = q;
}
__global__ void k_prep_c(const float* __restrict__ We, const float* __restrict__ be) {
    int j = threadIdx.x;
    float s = be[j];
    for (int k = 0; k < 128; k++) s = fmaf(C0, We[k * 128 + j], s);
    g_Cc[j] = s;
}

// ---------------------------------------------------------------- 3xTF32 GEMM
// C[Npad,128] = A[Npad,128] @ W[128,128] (+bias). Block 128x128, 8 warps 4x2,
// warp tile 32x64. BK=16.
#define GBK 16
#define AS_STR (GBK + 4)    // 20: frag-load conflict-free
#define BS_STR (128 + 8)    // 136: banks 8t+g, conflict-free
__global__ __launch_bounds__(256, 2) void gemm_tf32(
    int in_sel, const float* __restrict__ ext, int widx,
    const float* __restrict__ bias, int out_sel) {
    __shared__ float As_hi[128][AS_STR], As_lo[128][AS_STR];
    __shared__ float Bs_hi[GBK][BS_STR], Bs_lo[GBK][BS_STR];

    const float* A = (in_sel == 0) ? g_ha : (in_sel == 1) ? g_hb : ext;
    float* C = (out_sel == 2) ? g_X : g_Y;
    const float* Wh = g_Whi[widx];
    const float* Wl = g_Wlo[widx];

    const int tid = threadIdx.x;
    const int lane = tid & 31, warp = tid >> 5;
    const int wm = warp & 3, wn = warp >> 2;      // 4 x 2 warps
    const int g = lane >> 2, t = lane & 3;
    const int m0 = blockIdx.x * 128;

    float c[2][8][4];
#pragma unroll
    for (int mi = 0; mi < 2; mi++)
#pragma unroll
        for (int ni = 0; ni < 8; ni++)
#pragma unroll
            for (int q = 0; q < 4; q++) c[mi][ni][q] = 0.f;

    const int a_r = tid >> 2;            // 0..63, +64 second half
    const int a_c = (tid & 3) * 4;
    const int b_k = tid >> 5;            // 0..7, +8 second half
    const int b_c = (lane) * 4;

    for (int k0 = 0; k0 < 128; k0 += GBK) {
        // stage A (128x16), split to tf32 hi/lo
#pragma unroll
        for (int h = 0; h < 2; h++) {
            int row = a_r + h * 64;
            float4 v = *(const float4*)(A + (size_t)(m0 + row) * 128 + k0 + a_c);
            float4 vh, vl;
            vh.x = __uint_as_float(f2tf32(v.x)); vl.x = __uint_as_float(f2tf32(v.x - vh.x));
            vh.y = __uint_as_float(f2tf32(v.y)); vl.y = __uint_as_float(f2tf32(v.y - vh.y));
            vh.z = __uint_as_float(f2tf32(v.z)); vl.z = __uint_as_float(f2tf32(v.z - vh.z));
            vh.w = __uint_as_float(f2tf32(v.w)); vl.w = __uint_as_float(f2tf32(v.w - vh.w));
            *(float4*)&As_hi[row][a_c] = vh;
            *(float4*)&As_lo[row][a_c] = vl;
        }
        // stage B (16x128), pre-split in global
#pragma unroll
        for (int h = 0; h < 2; h++) {
            int kr = b_k + h * 8;
            *(float4*)&Bs_hi[kr][b_c] = *(const float4*)(Wh + (size_t)(k0 + kr) * 128 + b_c);
            *(float4*)&Bs_lo[kr][b_c] = *(const float4*)(Wl + (size_t)(k0 + kr) * 128 + b_c);
        }
        __syncthreads();

#pragma unroll
        for (int ks = 0; ks < GBK / 8; ks++) {
            uint32_t ah[2][4], al[2][4];
            const int kk = ks * 8 + t;
#pragma unroll
            for (int mi = 0; mi < 2; mi++) {
                int row = wm * 32 + mi * 16 + g;
                ah[mi][0] = __float_as_uint(As_hi[row][kk]);
                ah[mi][1] = __float_as_uint(As_hi[row + 8][kk]);
                ah[mi][2] = __float_as_uint(As_hi[row][kk + 4]);
                ah[mi][3] = __float_as_uint(As_hi[row + 8][kk + 4]);
                al[mi][0] = __float_as_uint(As_lo[row][kk]);
                al[mi][1] = __float_as_uint(As_lo[row + 8][kk]);
                al[mi][2] = __float_as_uint(As_lo[row][kk + 4]);
                al[mi][3] = __float_as_uint(As_lo[row + 8][kk + 4]);
            }
#pragma unroll
            for (int ni = 0; ni < 8; ni++) {
                int col = wn * 64 + ni * 8 + g;
                uint32_t bh0 = __float_as_uint(Bs_hi[kk][col]);
                uint32_t bh1 = __float_as_uint(Bs_hi[kk + 4][col]);
                uint32_t bl0 = __float_as_uint(Bs_lo[kk][col]);
                uint32_t bl1 = __float_as_uint(Bs_lo[kk + 4][col]);
#pragma unroll
                for (int mi = 0; mi < 2; mi++) {
                    mma_tf32(c[mi][ni], ah[mi], bh0, bh1);
                    mma_tf32(c[mi][ni], ah[mi], bl0, bl1);
                    mma_tf32(c[mi][ni], al[mi], bh0, bh1);
                }
            }
        }
        __syncthreads();
    }

    // epilogue
#pragma unroll
    for (int ni = 0; ni < 8; ni++) {
        int col = wn * 64 + ni * 8 + 2 * t;
        float b0 = bias ? bias[col] : 0.f;
        float b1 = bias ? bias[col + 1] : 0.f;
#pragma unroll
        for (int mi = 0; mi < 2; mi++) {
            int row = m0 + wm * 32 + mi * 16 + g;
            float2 o0 = make_float2(c[mi][ni][0] + b0, c[mi][ni][1] + b1);
            float2 o1 = make_float2(c[mi][ni][2] + b0, c[mi][ni][3] + b1);
            *(float2*)(C + (size_t)row * 128 + col) = o0;
            *(float2*)(C + (size_t)(row + 8) * 128 + col) = o1;
        }
    }
}

// ---------------------------------------------------------------- aggregations
// EdgeConv: h_b[d] = softplus( deg>0 ? P[d] + max_in Q[src] : 0 ). Warp/node.
__global__ void edgeconv_agg(int step1, const int* __restrict__ remap,
                             float* __restrict__ outExt, int N_) {
    int w = (blockIdx.x * blockDim.x + threadIdx.x) >> 5;
    if (w >= N_) return;
    int lane = threadIdx.x & 31;
    const float* P = step1 ? g_P20 : g_X;
    const float* Q = step1 ? g_Q20 : g_Y;
    int lo = g_rowptr[w], hi = g_rowptr[w + 1];
    float4 r;
    if (lo == hi) {
        r = make_float4(C0, C0, C0, C0);
    } else {
        float4 m = make_float4(-FLT_MAX, -FLT_MAX, -FLT_MAX, -FLT_MAX);
        for (int i = lo; i < hi; i++) {
            int s = g_csr[i].x;
            int qs = step1 ? remap[s] : s;
            float4 q = *(const float4*)(Q + (size_t)qs * 128 + lane * 4);
            m.x = fmaxf(m.x, q.x); m.y = fmaxf(m.y, q.y);
            m.z = fmaxf(m.z, q.z); m.w = fmaxf(m.w, q.w);
        }
        int pd = step1 ? remap[w] : w;
        float4 p = *(const float4*)(P + (size_t)pd * 128 + lane * 4);
        r = make_float4(sp(p.x + m.x), sp(p.y + m.y), sp(p.z + m.z), sp(p.w + m.w));
    }
    float* o = outExt ? outExt : g_hb;
    *(float4*)(o + (size_t)w * 128 + lane * 4) = r;
}

// GeneralConv: h_a[d] = softplus( sum_in (A[src] + (e<N ? Bv[e] : Cc)) + h_a[d] )
__global__ void genconv_agg(float* __restrict__ outExt, int N_) {
    int w = (blockIdx.x * blockDim.x + threadIdx.x) >> 5;
    if (w >= N_) return;
    int lane = threadIdx.x & 31;
    int lo = g_rowptr[w], hi = g_rowptr[w + 1];
    float4 acc = make_float4(0.f, 0.f, 0.f, 0.f);
    for (int i = lo; i < hi; i++) {
        int2 se = g_csr[i];
        float4 a = *(const float4*)(g_X + (size_t)se.x * 128 + lane * 4);
        const float* Bp = (se.y < N_) ? (g_Y + (size_t)se.y * 128) : g_Cc;
        float4 b = *(const float4*)(Bp + lane * 4);
        acc.x += a.x + b.x; acc.y += a.y + b.y;
        acc.z += a.z + b.z; acc.w += a.w + b.w;
    }
    float4 h = *(const float4*)(g_ha + (size_t)w * 128 + lane * 4);
    float4 r = make_float4(sp(acc.x + h.x), sp(acc.y + h.y), sp(acc.z + h.z), sp(acc.w + h.w));
    float* o = outExt ? outExt : g_ha;
    *(float4*)(o + (size_t)w * 128 + lane * 4) = r;
}

__global__ void k_fill_tail(float* __restrict__ dst4, size_t count4) {
    size_t i = (size_t)blockIdx.x * blockDim.x + threadIdx.x;
    if (i < count4) ((float4*)dst4)[i] = make_float4(C0, C0, C0, C0);
}

// ---------------------------------------------------------------- pool + MLP
__device__ __forceinline__ int lbound(const int* a, int n, int key) {
    int lo = 0, hi = n;
    while (lo < hi) {
        int mid = (lo + hi) >> 1;
        if (a[mid] < key) lo = mid + 1; else hi = mid;
    }
    return lo;
}
__global__ void k_pool(const int* __restrict__ batch, const float* __restrict__ HA, int N_) {
    int g = blockIdx.x, j = threadIdx.x;
    int lo = lbound(batch, N_, g), hi = lbound(batch, N_, g + 1);
    float acc = 0.f;
    for (int n = lo; n < hi; n++) acc += HA[(size_t)n * 128 + j];
    g_pooled[g * 128 + j] = acc;
}
__global__ void k_readout(const float* __restrict__ Wr1, const float* __restrict__ br1,
                          const float* __restrict__ Wr2, const float* __restrict__ br2,
                          const float* __restrict__ Wr3, const float* __restrict__ br3,
                          float* __restrict__ out) {
    int g = blockIdx.x, j = threadIdx.x;  // 64 threads
    __shared__ float p[128];
    __shared__ float h[64];
    __shared__ float part[2];
    p[j] = g_pooled[g * 128 + j];
    p[j + 64] = g_pooled[g * 128 + 64 + j];
    __syncthreads();
    float s = br1[j];
    for (int k = 0; k < 128; k++) s = fmaf(p[k], Wr1[k * 64 + j], s);
    h[j] = sp(s);
    __syncthreads();
    float s2 = br2[j];
    for (int k = 0; k < 64; k++) s2 = fmaf(h[k], Wr2[k * 64 + j], s2);
    float v = sp(s2) * Wr3[j];
#pragma unroll
    for (int o = 16; o; o >>= 1) v += __shfl_down_sync(0xffffffffu, v, o);
    if ((j & 31) == 0) part[j >> 5] = v;
    __syncthreads();
    if (j == 0) out[g] = part[0] + part[1] + br3[0];
}

// ---------------------------------------------------------------- launch
extern "C" void kernel_launch(void* const* d_in, const int* in_sizes, int n_in,
                              void* d_out, int out_size) {
    const int* x_ids = (const int*)d_in[0];
    const int* eaid  = (const int*)d_in[1];
    const int* eidx  = (const int*)d_in[2];
    const int* batch = (const int*)d_in[3];
    const float* emb_atom = (const float*)d_in[4];
    const float* emb_bond = (const float*)d_in[5];
    const float* Wb  = (const float*)d_in[6];
    const float* bb  = (const float*)d_in[7];
    const float* Wm  = (const float*)d_in[8];
    const float* bm  = (const float*)d_in[9];
    const float* We  = (const float*)d_in[10];
    const float* be  = (const float*)d_in[11];
    const float* Wr1 = (const float*)d_in[12];
    const float* br1 = (const float*)d_in[13];
    const float* Wr2 = (const float*)d_in[14];
    const float* br2 = (const float*)d_in[15];
    const float* Wr3 = (const float*)d_in[16];
    const float* br3 = (const float*)d_in[17];
    const int N = in_sizes[0];
    const int E = in_sizes[1];
    const int G = out_size - 128 * (N + E);   // 4096
    const int* srcp = eidx;
    const int* dstp = eidx + E;
    float* out = (float*)d_out;
    float* out_ha = out + G;
    float* out_hb = out_ha + (size_t)N * 128;

    const int nb = (N + 1023) / 1024;
    const int Npad = ((N + 127) / 128) * 128;
    const int gemm_grid = Npad / 128;
    const int agg_grid = (N + 7) / 8;

    // CSR by dst
    k_zero_deg<<<(N + 255) / 256, 256>>>(N);
    k_hist<<<(E + 255) / 256, 256>>>(dstp, E);
    k_scan1<<<nb, 1024>>>(N);
    k_scan2<<<1, 1024>>>(nb);
    k_scan3<<<(N + 255) / 256, 256>>>(N, E);
    k_fill_csr<<<(E + 255) / 256, 256>>>(srcp, dstp, E);

    // init + prep
    k_init_ha<<<(N * 128 + 255) / 256, 256>>>(x_ids, emb_atom, N);
    k_prep_wp<<<64, 256>>>(Wb);
    k_split<<<64, 256>>>(Wm, 0);
    k_split<<<64, 256>>>(We, 1);
    k_split_wb<<<64, 256>>>(Wb);
    k_prep_pq20<<<20, 128>>>(emb_bond, Wb, bb);
    k_prep_c<<<1, 128>>>(We, be);

    // ---- step 1 ----
    edgeconv_agg<<<agg_grid, 256>>>(1, eaid, nullptr, N);            // h_b1 -> g_hb
    gemm_tf32<<<gemm_grid, 256>>>(0, nullptr, 0, bm, 2);             // A1  = h_a0@Wm+bm -> X
    gemm_tf32<<<gemm_grid, 256>>>(1, nullptr, 1, be, 3);             // Bv1 = h_b1@We+be -> Y
    genconv_agg<<<agg_grid, 256>>>(nullptr, N);                      // h_a1 -> g_ha (in place)

    // ---- step 2 ----
    gemm_tf32<<<gemm_grid, 256>>>(1, nullptr, 2, bb, 2);             // P2 = h_b1@WP+bb -> X
    gemm_tf32<<<gemm_grid, 256>>>(1, nullptr, 3, nullptr, 3);        // Q2 = h_b1@W2 -> Y
    edgeconv_agg<<<agg_grid, 256>>>(0, nullptr, out_hb, N);          // h_b2 -> out_hb rows < N
    {
        size_t count4 = ((size_t)(E - N) * 128) / 4;                 // rows >= N are softplus(0)
        k_fill_tail<<<(unsigned)((count4 + 255) / 256), 256>>>(out_hb + (size_t)N * 128, count4);
    }
    gemm_tf32<<<gemm_grid, 256>>>(0, nullptr, 0, bm, 2);             // A2  = h_a1@Wm+bm -> X
    gemm_tf32<<<gemm_grid, 256>>>(4, out_hb, 1, be, 3);              // Bv2 = h_b2@We+be -> Y
    genconv_agg<<<agg_grid, 256>>>(out_ha, N);                       // h_a2 -> out_ha

    // ---- pool + readout ----
    k_pool<<<G, 128>>>(batch, out_ha, N);
    k_readout<<<G, 64>>>(Wr1, br1, Wr2, br2, Wr3, br3, out);
}

// round 6
// speedup vs baseline: 1.6432x; 1.1526x over previous
#include <cuda_runtime.h>
#include <cuda_bf16.h>
#include <math.h>
#include <float.h>
#include <stdint.h>

// ----------------------------------------------------------------------------
// MoleculeGCN forward.
//  - EdgeConv: msg = [x_i, x_j-x_i]@Wb = x_i@(W1-W2) + x_j@W2 -> per-node GEMMs
//  - Step-1 h_b: only 20 distinct rows -> 20-row P/Q tables
//  - h_b rows e>=N / deg-0 rows are constant softplus(0) -> h_b@W_edge constant
//  - dst-CSR gathers (no float atomics)
//  - GEMMs: 3xBF16 tensor-core mma m16n8k16 (hi/lo split) -> ~1e-5 accuracy
// ----------------------------------------------------------------------------

#define NMAX 100096   // multiple of 128 (GEMM tile M)
#define EMAX 400000
#define GMAX 4096
#define C0 0.69314718055994531f   // softplus(0) = ln 2

// scratch (device globals)
__device__ float g_ha[(size_t)NMAX * 128];
__device__ float g_hb[(size_t)NMAX * 128];
__device__ float g_X [(size_t)NMAX * 128];
__device__ float g_Y [(size_t)NMAX * 128];
__device__ int   g_deg[NMAX];
__device__ int   g_rowptr[NMAX + 1];
__device__ int   g_fill[NMAX];
__device__ int   g_bsum[1024];
__device__ int2  g_csr[EMAX];
__device__ float g_WP[128 * 128];
__device__ float g_P20[20 * 128];
__device__ float g_Q20[20 * 128];
__device__ float g_Cc[128];
__device__ float g_pooled[GMAX * 128];
// pre-split, pre-TRANSPOSED bf16 weights [n][k]: 0=Wm 1=We 2=WP(W1-W2) 3=W2
__device__ __nv_bfloat16 g_WTh[4][16384];
__device__ __nv_bfloat16 g_WTl[4][16384];

__device__ __forceinline__ float sp(float x) {
    return fmaxf(x, 0.f) + log1pf(__expf(-fabsf(x)));
}
__device__ __forceinline__ void mma_bf16(float* d, const uint32_t* a, uint32_t b0, uint32_t b1) {
    asm volatile(
        "mma.sync.aligned.m16n8k16.row.col.f32.bf16.bf16.f32 "
        "{%0,%1,%2,%3}, {%4,%5,%6,%7}, {%8,%9}, {%0,%1,%2,%3};"
        : "+f"(d[0]), "+f"(d[1]), "+f"(d[2]), "+f"(d[3])
        : "r"(a[0]), "r"(a[1]), "r"(a[2]), "r"(a[3]), "r"(b0), "r"(b1));
}

// ---------------------------------------------------------------- CSR build
__global__ void k_zero_deg(int N_) {
    int i = blockIdx.x * blockDim.x + threadIdx.x;
    if (i < N_) g_deg[i] = 0;
}
__global__ void k_hist(const int* __restrict__ dst, int E_) {
    int e = blockIdx.x * blockDim.x + threadIdx.x;
    if (e < E_) atomicAdd(&g_deg[dst[e]], 1);
}
__global__ __launch_bounds__(1024) void k_scan1(int N_) {
    int t = threadIdx.x, b = blockIdx.x, i = b * 1024 + t;
    int v = (i < N_) ? g_deg[i] : 0;
    int lane = t & 31, wid = t >> 5;
    int incl = v;
#pragma unroll
    for (int o = 1; o < 32; o <<= 1) {
        int u = __shfl_up_sync(0xffffffffu, incl, o);
        if (lane >= o) incl += u;
    }
    __shared__ int ws[32];
    if (lane == 31) ws[wid] = incl;
    __syncthreads();
    if (wid == 0) {
        int x = ws[lane];
#pragma unroll
        for (int o = 1; o < 32; o <<= 1) {
            int u = __shfl_up_sync(0xffffffffu, x, o);
            if (lane >= o) x += u;
        }
        ws[lane] = x;
    }
    __syncthreads();
    int off = wid ? ws[wid - 1] : 0;
    if (i < N_) g_rowptr[i] = off + incl - v;
    if (t == 1023) g_bsum[b] = off + incl;
}
__global__ __launch_bounds__(1024) void k_scan2(int nb) {
    int t = threadIdx.x;
    int v = (t < nb) ? g_bsum[t] : 0;
    int lane = t & 31, wid = t >> 5;
    int incl = v;
#pragma unroll
    for (int o = 1; o < 32; o <<= 1) {
        int u = __shfl_up_sync(0xffffffffu, incl, o);
        if (lane >= o) incl += u;
    }
    __shared__ int ws[32];
    if (lane == 31) ws[wid] = incl;
    __syncthreads();
    if (wid == 0) {
        int x = ws[lane];
#pragma unroll
        for (int o = 1; o < 32; o <<= 1) {
            int u = __shfl_up_sync(0xffffffffu, x, o);
            if (lane >= o) x += u;
        }
        ws[lane] = x;
    }
    __syncthreads();
    int off = wid ? ws[wid - 1] : 0;
    if (t < nb) g_bsum[t] = off + incl - v;
}
__global__ void k_scan3(int N_, int E_) {
    int i = blockIdx.x * blockDim.x + threadIdx.x;
    if (i < N_) {
        int r = g_rowptr[i] + g_bsum[i >> 10];
        g_rowptr[i] = r;
        g_fill[i] = r;
    }
    if (i == 0) g_rowptr[N_] = E_;
}
__global__ void k_fill_csr(const int* __restrict__ src, const int* __restrict__ dst, int E_) {
    int e = blockIdx.x * blockDim.x + threadIdx.x;
    if (e < E_) {
        int p = atomicAdd(&g_fill[dst[e]], 1);
        g_csr[p] = make_int2(src[e], e);
    }
}

// ---------------------------------------------------------------- init / prep
__global__ void k_init_ha(const int* __restrict__ xids, const float* __restrict__ ea, int N_) {
    int i = blockIdx.x * blockDim.x + threadIdx.x;
    if (i < N_ * 128) {
        int n = i >> 7, c = i & 127;
        g_ha[i] = sp(ea[xids[n] * 128 + c]);
    }
}
__global__ void k_prep_wp(const float* __restrict__ Wb) {
    int i = blockIdx.x * blockDim.x + threadIdx.x;
    if (i < 16384) g_WP[i] = Wb[i] - Wb[i + 16384];
}
// transpose + split fp32 weight W[k][n] -> bf16 hi/lo WT[n][k]
__global__ void k_splitT(const float* __restrict__ W, int widx) {
    int i = blockIdx.x * blockDim.x + threadIdx.x;
    if (i < 16384) {
        int n = i >> 7, k = i & 127;
        float v = W[k * 128 + n];
        __nv_bfloat16 hi = __float2bfloat16_rn(v);
        g_WTh[widx][i] = hi;
        g_WTl[widx][i] = __float2bfloat16_rn(v - __bfloat162float(hi));
    }
}
__global__ void k_splitT_wb(const float* __restrict__ Wb) {
    int i = blockIdx.x * blockDim.x + threadIdx.x;
    if (i < 16384) {
        int n = i >> 7, k = i & 127;
        float w2 = Wb[(128 + k) * 128 + n];
        float wp = Wb[k * 128 + n] - w2;
        __nv_bfloat16 hi = __float2bfloat16_rn(wp);
        g_WTh[2][i] = hi;
        g_WTl[2][i] = __float2bfloat16_rn(wp - __bfloat162float(hi));
        hi = __float2bfloat16_rn(w2);
        g_WTh[3][i] = hi;
        g_WTl[3][i] = __float2bfloat16_rn(w2 - __bfloat162float(hi));
    }
}
__global__ void k_prep_pq20(const float* __restrict__ eb, const float* __restrict__ Wb,
                            const float* __restrict__ bb) {
    __shared__ float h[128];
    int k = blockIdx.x, j = threadIdx.x;
    h[j] = sp(eb[k * 128 + j]);
    __syncthreads();
    float p = bb[j], q = 0.f;
    for (int kk = 0; kk < 128; kk++) {
        float hv = h[kk];
        p = fmaf(hv, g_WP[kk * 128 + j], p);
        q = fmaf(hv, Wb[(128 + kk) * 128 + j], q);
    }
    g_P20[k * 128 + j] = p;
    g_Q20[k * 128 + j] = q;
}
__global__ void k_prep_c(const float* __restrict__ We, const float* __restrict__ be) {
    int j = threadIdx.x;
    float s = be[j];
    for (int k = 0; k < 128; k++) s = fmaf(C0, We[k * 128 + j], s);
    g_Cc[j] = s;
}

// ---------------------------------------------------------------- 3xBF16 GEMM
// C[Npad,128] = A[Npad,128] @ W[128,128] (+bias). Block 128x128, 8 warps 4x2,
// warp tile 32x64. K chunk = 16 (one m16n8k16 step per pass).
#define ASTR 24   // b16 stride: 12 words -> frag loads 12g+t conflict-free
struct alignas(16) bf8 { __nv_bfloat16 v[8]; };
__global__ __launch_bounds__(256, 2) void gemm_bf16(
    int in_sel, const float* __restrict__ ext, int widx,
    const float* __restrict__ bias, int out_sel) {
    __shared__ __nv_bfloat16 As_h[128][ASTR], As_l[128][ASTR];
    __shared__ __nv_bfloat16 Bt_h[128][ASTR], Bt_l[128][ASTR];

    const float* A = (in_sel == 0) ? g_ha : (in_sel == 1) ? g_hb : ext;
    float* C = (out_sel == 2) ? g_X : g_Y;

    const int tid = threadIdx.x;
    const int lane = tid & 31, warp = tid >> 5;
    const int wm = warp & 3, wn = warp >> 2;      // 4 x 2 warps
    const int g = lane >> 2, t = lane & 3;
    const int m0 = blockIdx.x * 128;

    float c[2][8][4];
#pragma unroll
    for (int mi = 0; mi < 2; mi++)
#pragma unroll
        for (int ni = 0; ni < 8; ni++)
#pragma unroll
            for (int q = 0; q < 4; q++) c[mi][ni][q] = 0.f;

    const int a_row = tid >> 1;           // 0..127
    const int a_colq = (tid & 1) * 8;     // 0 or 8
    const int b_n = tid & 127;
    const int b_half = tid >> 7;          // 0 = hi, 1 = lo
    const __nv_bfloat16* bsrc = (b_half ? g_WTl[widx] : g_WTh[widx]) + b_n * 128;

#pragma unroll
    for (int k0 = 0; k0 < 128; k0 += 16) {
        // stage A (128x16 fp32 -> bf16 hi/lo)
        {
            const float* ap = A + (size_t)(m0 + a_row) * 128 + k0 + a_colq;
            float4 v0 = *(const float4*)ap;
            float4 v1 = *(const float4*)(ap + 4);
            float vv[8] = {v0.x, v0.y, v0.z, v0.w, v1.x, v1.y, v1.z, v1.w};
            bf8 hi, lo;
#pragma unroll
            for (int q = 0; q < 8; q++) {
                __nv_bfloat16 h = __float2bfloat16_rn(vv[q]);
                hi.v[q] = h;
                lo.v[q] = __float2bfloat16_rn(vv[q] - __bfloat162float(h));
            }
            *(uint4*)&As_h[a_row][a_colq] = *(const uint4*)&hi;
            *(uint4*)&As_l[a_row][a_colq] = *(const uint4*)&lo;
        }
        // stage Bt chunk (128 n-rows x 16 k, hi or lo per thread-half)
        {
            __nv_bfloat16* bd = (b_half ? &Bt_l[b_n][0] : &Bt_h[b_n][0]);
            *(uint4*)(bd)     = *(const uint4*)(bsrc + k0);
            *(uint4*)(bd + 8) = *(const uint4*)(bsrc + k0 + 8);
        }
        __syncthreads();

        uint32_t ah[2][4], al[2][4];
#pragma unroll
        for (int mi = 0; mi < 2; mi++) {
            int r = wm * 32 + mi * 16 + g;
            ah[mi][0] = *(const uint32_t*)&As_h[r][2 * t];
            ah[mi][1] = *(const uint32_t*)&As_h[r + 8][2 * t];
            ah[mi][2] = *(const uint32_t*)&As_h[r][2 * t + 8];
            ah[mi][3] = *(const uint32_t*)&As_h[r + 8][2 * t + 8];
            al[mi][0] = *(const uint32_t*)&As_l[r][2 * t];
            al[mi][1] = *(const uint32_t*)&As_l[r + 8][2 * t];
            al[mi][2] = *(const uint32_t*)&As_l[r][2 * t + 8];
            al[mi][3] = *(const uint32_t*)&As_l[r + 8][2 * t + 8];
        }
#pragma unroll
        for (int ni = 0; ni < 8; ni++) {
            int n = wn * 64 + ni * 8 + g;
            uint32_t bh0 = *(const uint32_t*)&Bt_h[n][2 * t];
            uint32_t bh1 = *(const uint32_t*)&Bt_h[n][2 * t + 8];
            uint32_t bl0 = *(const uint32_t*)&Bt_l[n][2 * t];
            uint32_t bl1 = *(const uint32_t*)&Bt_l[n][2 * t + 8];
#pragma unroll
            for (int mi = 0; mi < 2; mi++) {
                mma_bf16(c[mi][ni], ah[mi], bh0, bh1);
                mma_bf16(c[mi][ni], ah[mi], bl0, bl1);
                mma_bf16(c[mi][ni], al[mi], bh0, bh1);
            }
        }
        __syncthreads();
    }

    // epilogue
#pragma unroll
    for (int ni = 0; ni < 8; ni++) {
        int col = wn * 64 + ni * 8 + 2 * t;
        float b0 = bias ? bias[col] : 0.f;
        float b1 = bias ? bias[col + 1] : 0.f;
#pragma unroll
        for (int mi = 0; mi < 2; mi++) {
            int row = m0 + wm * 32 + mi * 16 + g;
            float2 o0 = make_float2(c[mi][ni][0] + b0, c[mi][ni][1] + b1);
            float2 o1 = make_float2(c[mi][ni][2] + b0, c[mi][ni][3] + b1);
            *(float2*)(C + (size_t)row * 128 + col) = o0;
            *(float2*)(C + (size_t)(row + 8) * 128 + col) = o1;
        }
    }
}

// ---------------------------------------------------------------- aggregations
// EdgeConv: h_b[d] = softplus( deg>0 ? P[d] + max_in Q[src] : 0 ). Warp/node.
__global__ void edgeconv_agg(int step1, const int* __restrict__ remap,
                             float* __restrict__ outExt, int N_) {
    int w = (blockIdx.x * blockDim.x + threadIdx.x) >> 5;
    if (w >= N_) return;
    int lane = threadIdx.x & 31;
    const float* P = step1 ? g_P20 : g_X;
    const float* Q = step1 ? g_Q20 : g_Y;
    int lo = g_rowptr[w], hi = g_rowptr[w + 1];
    float4 r;
    if (lo == hi) {
        r = make_float4(C0, C0, C0, C0);
    } else {
        float4 m = make_float4(-FLT_MAX, -FLT_MAX, -FLT_MAX, -FLT_MAX);
        for (int i = lo; i < hi; i++) {
            int s = g_csr[i].x;
            int qs = step1 ? remap[s] : s;
            float4 q = *(const float4*)(Q + (size_t)qs * 128 + lane * 4);
            m.x = fmaxf(m.x, q.x); m.y = fmaxf(m.y, q.y);
            m.z = fmaxf(m.z, q.z); m.w = fmaxf(m.w, q.w);
        }
        int pd = step1 ? remap[w] : w;
        float4 p = *(const float4*)(P + (size_t)pd * 128 + lane * 4);
        r = make_float4(sp(p.x + m.x), sp(p.y + m.y), sp(p.z + m.z), sp(p.w + m.w));
    }
    float* o = outExt ? outExt : g_hb;
    *(float4*)(o + (size_t)w * 128 + lane * 4) = r;
}

// GeneralConv: h_a[d] = softplus( sum_in (A[src] + (e<N ? Bv[e] : Cc)) + h_a[d] )
__global__ void genconv_agg(float* __restrict__ outExt, int N_) {
    int w = (blockIdx.x * blockDim.x + threadIdx.x) >> 5;
    if (w >= N_) return;
    int lane = threadIdx.x & 31;
    int lo = g_rowptr[w], hi = g_rowptr[w + 1];
    float4 acc = make_float4(0.f, 0.f, 0.f, 0.f);
    for (int i = lo; i < hi; i++) {
        int2 se = g_csr[i];
        float4 a = *(const float4*)(g_X + (size_t)se.x * 128 + lane * 4);
        const float* Bp = (se.y < N_) ? (g_Y + (size_t)se.y * 128) : g_Cc;
        float4 b = *(const float4*)(Bp + lane * 4);
        acc.x += a.x + b.x; acc.y += a.y + b.y;
        acc.z += a.z + b.z; acc.w += a.w + b.w;
    }
    float4 h = *(const float4*)(g_ha + (size_t)w * 128 + lane * 4);
    float4 r = make_float4(sp(acc.x + h.x), sp(acc.y + h.y), sp(acc.z + h.z), sp(acc.w + h.w));
    float* o = outExt ? outExt : g_ha;
    *(float4*)(o + (size_t)w * 128 + lane * 4) = r;
}

__global__ void k_fill_tail(float* __restrict__ dst4, size_t count4) {
    size_t i = (size_t)blockIdx.x * blockDim.x + threadIdx.x;
    if (i < count4) ((float4*)dst4)[i] = make_float4(C0, C0, C0, C0);
}

// ---------------------------------------------------------------- pool + MLP
__device__ __forceinline__ int lbound(const int* a, int n, int key) {
    int lo = 0, hi = n;
    while (lo < hi) {
        int mid = (lo + hi) >> 1;
        if (a[mid] < key) lo = mid + 1; else hi = mid;
    }
    return lo;
}
__global__ void k_pool(const int* __restrict__ batch, const float* __restrict__ HA, int N_) {
    int g = blockIdx.x, j = threadIdx.x;
    int lo = lbound(batch, N_, g), hi = lbound(batch, N_, g + 1);
    float acc = 0.f;
    for (int n = lo; n < hi; n++) acc += HA[(size_t)n * 128 + j];
    g_pooled[g * 128 + j] = acc;
}
__global__ void k_readout(const float* __restrict__ Wr1, const float* __restrict__ br1,
                          const float* __restrict__ Wr2, const float* __restrict__ br2,
                          const float* __restrict__ Wr3, const float* __restrict__ br3,
                          float* __restrict__ out) {
    int g = blockIdx.x, j = threadIdx.x;  // 64 threads
    __shared__ float p[128];
    __shared__ float h[64];
    __shared__ float part[2];
    p[j] = g_pooled[g * 128 + j];
    p[j + 64] = g_pooled[g * 128 + 64 + j];
    __syncthreads();
    float s = br1[j];
    for (int k = 0; k < 128; k++) s = fmaf(p[k], Wr1[k * 64 + j], s);
    h[j] = sp(s);
    __syncthreads();
    float s2 = br2[j];
    for (int k = 0; k < 64; k++) s2 = fmaf(h[k], Wr2[k * 64 + j], s2);
    float v = sp(s2) * Wr3[j];
#pragma unroll
    for (int o = 16; o; o >>= 1) v += __shfl_down_sync(0xffffffffu, v, o);
    if ((j & 31) == 0) part[j >> 5] = v;
    __syncthreads();
    if (j == 0) out[g] = part[0] + part[1] + br3[0];
}

// ---------------------------------------------------------------- launch
extern "C" void kernel_launch(void* const* d_in, const int* in_sizes, int n_in,
                              void* d_out, int out_size) {
    const int* x_ids = (const int*)d_in[0];
    const int* eaid  = (const int*)d_in[1];
    const int* eidx  = (const int*)d_in[2];
    const int* batch = (const int*)d_in[3];
    const float* emb_atom = (const float*)d_in[4];
    const float* emb_bond = (const float*)d_in[5];
    const float* Wb  = (const float*)d_in[6];
    const float* bb  = (const float*)d_in[7];
    const float* Wm  = (const float*)d_in[8];
    const float* bm  = (const float*)d_in[9];
    const float* We  = (const float*)d_in[10];
    const float* be  = (const float*)d_in[11];
    const float* Wr1 = (const float*)d_in[12];
    const float* br1 = (const float*)d_in[13];
    const float* Wr2 = (const float*)d_in[14];
    const float* br2 = (const float*)d_in[15];
    const float* Wr3 = (const float*)d_in[16];
    const float* br3 = (const float*)d_in[17];
    const int N = in_sizes[0];
    const int E = in_sizes[1];
    const int G = out_size - 128 * (N + E);   // 4096
    const int* srcp = eidx;
    const int* dstp = eidx + E;
    float* out = (float*)d_out;
    float* out_ha = out + G;
    float* out_hb = out_ha + (size_t)N * 128;

    const int nb = (N + 1023) / 1024;
    const int Npad = ((N + 127) / 128) * 128;
    const int gemm_grid = Npad / 128;
    const int agg_grid = (N + 7) / 8;

    // CSR by dst
    k_zero_deg<<<(N + 255) / 256, 256>>>(N);
    k_hist<<<(E + 255) / 256, 256>>>(dstp, E);
    k_scan1<<<nb, 1024>>>(N);
    k_scan2<<<1, 1024>>>(nb);
    k_scan3<<<(N + 255) / 256, 256>>>(N, E);
    k_fill_csr<<<(E + 255) / 256, 256>>>(srcp, dstp, E);

    // init + prep
    k_init_ha<<<(N * 128 + 255) / 256, 256>>>(x_ids, emb_atom, N);
    k_prep_wp<<<64, 256>>>(Wb);
    k_splitT<<<64, 256>>>(Wm, 0);
    k_splitT<<<64, 256>>>(We, 1);
    k_splitT_wb<<<64, 256>>>(Wb);
    k_prep_pq20<<<20, 128>>>(emb_bond, Wb, bb);
    k_prep_c<<<1, 128>>>(We, be);

    // ---- step 1 ----
    edgeconv_agg<<<agg_grid, 256>>>(1, eaid, nullptr, N);            // h_b1 -> g_hb
    gemm_bf16<<<gemm_grid, 256>>>(0, nullptr, 0, bm, 2);             // A1  = h_a0@Wm+bm -> X
    gemm_bf16<<<gemm_grid, 256>>>(1, nullptr, 1, be, 3);             // Bv1 = h_b1@We+be -> Y
    genconv_agg<<<agg_grid, 256>>>(nullptr, N);                      // h_a1 -> g_ha (in place)

    // ---- step 2 ----
    gemm_bf16<<<gemm_grid, 256>>>(1, nullptr, 2, bb, 2);             // P2 = h_b1@WP+bb -> X
    gemm_bf16<<<gemm_grid, 256>>>(1, nullptr, 3, nullptr, 3);        // Q2 = h_b1@W2 -> Y
    edgeconv_agg<<<agg_grid, 256>>>(0, nullptr, out_hb, N);          // h_b2 -> out_hb rows < N
    {
        size_t count4 = ((size_t)(E - N) * 128) / 4;                 // rows >= N are softplus(0)
        k_fill_tail<<<(unsigned)((count4 + 255) / 256), 256>>>(out_hb + (size_t)N * 128, count4);
    }
    gemm_bf16<<<gemm_grid, 256>>>(0, nullptr, 0, bm, 2);             // A2  = h_a1@Wm+bm -> X
    gemm_bf16<<<gemm_grid, 256>>>(4, out_hb, 1, be, 3);              // Bv2 = h_b2@We+be -> Y
    genconv_agg<<<agg_grid, 256>>>(out_ha, N);                       // h_a2 -> out_ha

    // ---- pool + readout ----
    k_pool<<<G, 128>>>(batch, out_ha, N);
    k_readout<<<G, 64>>>(Wr1, br1, Wr2, br2, Wr3, br3, out);
}

// round 8
// speedup vs baseline: 1.8312x; 1.1144x over previous
#include <cuda_runtime.h>
#include <cuda_bf16.h>
#include <math.h>
#include <float.h>
#include <stdint.h>

// ----------------------------------------------------------------------------
// MoleculeGCN forward.
//  - EdgeConv: msg = [x_i, x_j-x_i]@Wb = x_i@(W1-W2) + x_j@W2 -> per-node GEMMs
//  - Step-1 h_b: only 20 distinct rows -> 20-row P/Q tables
//  - h_b rows e>=N / deg-0 rows are constant softplus(0) -> h_b@W_edge constant
//  - dst-CSR gathers (no float atomics)
//  - GEMMs: 3xBF16 mma m16n8k16, double-buffered cp.async pipeline
// ----------------------------------------------------------------------------

#define NMAX 100096   // multiple of 128 (GEMM tile M)
#define EMAX 400000
#define GMAX 4096
#define C0 0.69314718055994531f   // softplus(0) = ln 2

// scratch (device globals)
__device__ float g_ha[(size_t)NMAX * 128];
__device__ float g_hb[(size_t)NMAX * 128];
__device__ float g_X [(size_t)NMAX * 128];
__device__ float g_Y [(size_t)NMAX * 128];
__device__ int   g_deg[NMAX];
__device__ int   g_rowptr[NMAX + 1];
__device__ int   g_fill[NMAX];
__device__ int   g_bsum[1024];
__device__ int2  g_csr[EMAX];
__device__ float g_WP[128 * 128];
__device__ float g_P20[20 * 128];
__device__ float g_Q20[20 * 128];
__device__ float g_Cc[128];
__device__ float g_pooled[GMAX * 128];
// pre-split, pre-TRANSPOSED bf16 weights [n][k]: 0=Wm 1=We 2=WP(W1-W2) 3=W2
__device__ __nv_bfloat16 g_WTh[4][16384];
__device__ __nv_bfloat16 g_WTl[4][16384];

__device__ __forceinline__ float sp(float x) {
    return fmaxf(x, 0.f) + log1pf(__expf(-fabsf(x)));
}
__device__ __forceinline__ void mma_bf16(float* d, const uint32_t* a, uint32_t b0, uint32_t b1) {
    asm volatile(
        "mma.sync.aligned.m16n8k16.row.col.f32.bf16.bf16.f32 "
        "{%0,%1,%2,%3}, {%4,%5,%6,%7}, {%8,%9}, {%0,%1,%2,%3};"
        : "+f"(d[0]), "+f"(d[1]), "+f"(d[2]), "+f"(d[3])
        : "r"(a[0]), "r"(a[1]), "r"(a[2]), "r"(a[3]), "r"(b0), "r"(b1));
}
__device__ __forceinline__ void cp16(void* sdst, const void* gsrc) {
    uint32_t s = (uint32_t)__cvta_generic_to_shared(sdst);
    asm volatile("cp.async.cg.shared.global [%0], [%1], 16;" :: "r"(s), "l"(gsrc));
}

// ---------------------------------------------------------------- CSR build
__global__ void k_zero_deg(int N_) {
    int i = blockIdx.x * blockDim.x + threadIdx.x;
    if (i < N_) g_deg[i] = 0;
}
__global__ void k_hist(const int* __restrict__ dst, int E_) {
    int e = blockIdx.x * blockDim.x + threadIdx.x;
    if (e < E_) atomicAdd(&g_deg[dst[e]], 1);
}
__global__ __launch_bounds__(1024) void k_scan1(int N_) {
    int t = threadIdx.x, b = blockIdx.x, i = b * 1024 + t;
    int v = (i < N_) ? g_deg[i] : 0;
    int lane = t & 31, wid = t >> 5;
    int incl = v;
#pragma unroll
    for (int o = 1; o < 32; o <<= 1) {
        int u = __shfl_up_sync(0xffffffffu, incl, o);
        if (lane >= o) incl += u;
    }
    __shared__ int ws[32];
    if (lane == 31) ws[wid] = incl;
    __syncthreads();
    if (wid == 0) {
        int x = ws[lane];
#pragma unroll
        for (int o = 1; o < 32; o <<= 1) {
            int u = __shfl_up_sync(0xffffffffu, x, o);
            if (lane >= o) x += u;
        }
        ws[lane] = x;
    }
    __syncthreads();
    int off = wid ? ws[wid - 1] : 0;
    if (i < N_) g_rowptr[i] = off + incl - v;
    if (t == 1023) g_bsum[b] = off + incl;
}
__global__ __launch_bounds__(1024) void k_scan2(int nb) {
    int t = threadIdx.x;
    int v = (t < nb) ? g_bsum[t] : 0;
    int lane = t & 31, wid = t >> 5;
    int incl = v;
#pragma unroll
    for (int o = 1; o < 32; o <<= 1) {
        int u = __shfl_up_sync(0xffffffffu, incl, o);
        if (lane >= o) incl += u;
    }
    __shared__ int ws[32];
    if (lane == 31) ws[wid] = incl;
    __syncthreads();
    if (wid == 0) {
        int x = ws[lane];
#pragma unroll
        for (int o = 1; o < 32; o <<= 1) {
            int u = __shfl_up_sync(0xffffffffu, x, o);
            if (lane >= o) x += u;
        }
        ws[lane] = x;
    }
    __syncthreads();
    int off = wid ? ws[wid - 1] : 0;
    if (t < nb) g_bsum[t] = off + incl - v;
}
__global__ void k_scan3(int N_, int E_) {
    int i = blockIdx.x * blockDim.x + threadIdx.x;
    if (i < N_) {
        int r = g_rowptr[i] + g_bsum[i >> 10];
        g_rowptr[i] = r;
        g_fill[i] = r;
    }
    if (i == 0) g_rowptr[N_] = E_;
}
__global__ void k_fill_csr(const int* __restrict__ src, const int* __restrict__ dst, int E_) {
    int e = blockIdx.x * blockDim.x + threadIdx.x;
    if (e < E_) {
        int p = atomicAdd(&g_fill[dst[e]], 1);
        g_csr[p] = make_int2(src[e], e);
    }
}

// ---------------------------------------------------------------- init / prep
__global__ void k_init_ha(const int* __restrict__ xids, const float* __restrict__ ea, int N_) {
    int i = blockIdx.x * blockDim.x + threadIdx.x;
    if (i < N_ * 128) {
        int n = i >> 7, c = i & 127;
        g_ha[i] = sp(ea[xids[n] * 128 + c]);
    }
}
__global__ void k_prep_wp(const float* __restrict__ Wb) {
    int i = blockIdx.x * blockDim.x + threadIdx.x;
    if (i < 16384) g_WP[i] = Wb[i] - Wb[i + 16384];
}
// transpose + split fp32 weight W[k][n] -> bf16 hi/lo WT[n][k]
__global__ void k_splitT(const float* __restrict__ W, int widx) {
    int i = blockIdx.x * blockDim.x + threadIdx.x;
    if (i < 16384) {
        int n = i >> 7, k = i & 127;
        float v = W[k * 128 + n];
        __nv_bfloat16 hi = __float2bfloat16_rn(v);
        g_WTh[widx][i] = hi;
        g_WTl[widx][i] = __float2bfloat16_rn(v - __bfloat162float(hi));
    }
}
__global__ void k_splitT_wb(const float* __restrict__ Wb) {
    int i = blockIdx.x * blockDim.x + threadIdx.x;
    if (i < 16384) {
        int n = i >> 7, k = i & 127;
        float w2 = Wb[(128 + k) * 128 + n];
        float wp = Wb[k * 128 + n] - w2;
        __nv_bfloat16 hi = __float2bfloat16_rn(wp);
        g_WTh[2][i] = hi;
        g_WTl[2][i] = __float2bfloat16_rn(wp - __bfloat162float(hi));
        hi = __float2bfloat16_rn(w2);
        g_WTh[3][i] = hi;
        g_WTl[3][i] = __float2bfloat16_rn(w2 - __bfloat162float(hi));
    }
}
__global__ void k_prep_pq20(const float* __restrict__ eb, const float* __restrict__ Wb,
                            const float* __restrict__ bb) {
    __shared__ float h[128];
    int k = blockIdx.x, j = threadIdx.x;
    h[j] = sp(eb[k * 128 + j]);
    __syncthreads();
    float p = bb[j], q = 0.f;
    for (int kk = 0; kk < 128; kk++) {
        float hv = h[kk];
        p = fmaf(hv, g_WP[kk * 128 + j], p);
        q = fmaf(hv, Wb[(128 + kk) * 128 + j], q);
    }
    g_P20[k * 128 + j] = p;
    g_Q20[k * 128 + j] = q;
}
__global__ void k_prep_c(const float* __restrict__ We, const float* __restrict__ be) {
    int j = threadIdx.x;
    float s = be[j];
    for (int k = 0; k < 128; k++) s = fmaf(C0, We[k * 128 + j], s);
    g_Cc[j] = s;
}

// ---------------------------------------------------------------- 3xBF16 GEMM
// C[Npad,128] = A[Npad,128] @ W[128,128] (+bias). Block 128x128, 8 warps 4x2,
// warp tile 32x64. Double-buffered k16 chunks: cp.async B, LDG-prefetched A,
// one __syncthreads per chunk.
#define ASTR 24   // b16 stride: 12 words -> frag loads 12g+t conflict-free
struct alignas(16) bf8 { __nv_bfloat16 v[8]; };
__global__ __launch_bounds__(256, 2) void gemm_bf16(
    int in_sel, const float* __restrict__ ext, int widx,
    const float* __restrict__ bias, int out_sel) {
    __shared__ __nv_bfloat16 As_h[2][128][ASTR], As_l[2][128][ASTR];
    __shared__ __nv_bfloat16 Bt_h[2][128][ASTR], Bt_l[2][128][ASTR];

    const float* A = (in_sel == 0) ? g_ha : (in_sel == 1) ? g_hb : ext;
    float* C = (out_sel == 2) ? g_X : g_Y;

    const int tid = threadIdx.x;
    const int lane = tid & 31, warp = tid >> 5;
    const int wm = warp & 3, wn = warp >> 2;      // 4 x 2 warps
    const int g = lane >> 2, t = lane & 3;
    const int m0 = blockIdx.x * 128;

    float c[2][8][4];
#pragma unroll
    for (int mi = 0; mi < 2; mi++)
#pragma unroll
        for (int ni = 0; ni < 8; ni++)
#pragma unroll
            for (int q = 0; q < 4; q++) c[mi][ni][q] = 0.f;

    const int a_row = tid >> 1;           // 0..127
    const int a_colq = (tid & 1) * 8;     // 0 or 8
    const float* a_base = A + (size_t)(m0 + a_row) * 128 + a_colq;
    const int b_row = tid >> 1;           // 0..127 (n index)
    const int b_col8 = (tid & 1) * 8;     // 0 or 8 within k16 chunk
    const __nv_bfloat16* bh_src = g_WTh[widx] + b_row * 128 + b_col8;
    const __nv_bfloat16* bl_src = g_WTl[widx] + b_row * 128 + b_col8;

    float vv[8];
    // prologue: chunk 0
    {
        float4 v0 = *(const float4*)(a_base);
        float4 v1 = *(const float4*)(a_base + 4);
        vv[0] = v0.x; vv[1] = v0.y; vv[2] = v0.z; vv[3] = v0.w;
        vv[4] = v1.x; vv[5] = v1.y; vv[6] = v1.z; vv[7] = v1.w;
        cp16(&Bt_h[0][b_row][b_col8], bh_src);
        cp16(&Bt_l[0][b_row][b_col8], bl_src);
        asm volatile("cp.async.commit_group;");
        bf8 hi, lo;
#pragma unroll
        for (int q = 0; q < 8; q++) {
            __nv_bfloat16 h = __float2bfloat16_rn(vv[q]);
            hi.v[q] = h;
            lo.v[q] = __float2bfloat16_rn(vv[q] - __bfloat162float(h));
        }
        *(uint4*)&As_h[0][a_row][a_colq] = *(const uint4*)&hi;
        *(uint4*)&As_l[0][a_row][a_colq] = *(const uint4*)&lo;
        asm volatile("cp.async.wait_group 0;");
    }
    __syncthreads();

#pragma unroll
    for (int k = 0; k < 8; k++) {
        const int buf = k & 1, nbuf = buf ^ 1;
        if (k < 7) {
            const int k1 = (k + 1) * 16;
            float4 v0 = *(const float4*)(a_base + k1);
            float4 v1 = *(const float4*)(a_base + k1 + 4);
            vv[0] = v0.x; vv[1] = v0.y; vv[2] = v0.z; vv[3] = v0.w;
            vv[4] = v1.x; vv[5] = v1.y; vv[6] = v1.z; vv[7] = v1.w;
            cp16(&Bt_h[nbuf][b_row][b_col8], bh_src + k1);
            cp16(&Bt_l[nbuf][b_row][b_col8], bl_src + k1);
            asm volatile("cp.async.commit_group;");
        }

        uint32_t ah[2][4], al[2][4];
#pragma unroll
        for (int mi = 0; mi < 2; mi++) {
            int r = wm * 32 + mi * 16 + g;
            ah[mi][0] = *(const uint32_t*)&As_h[buf][r][2 * t];
            ah[mi][1] = *(const uint32_t*)&As_h[buf][r + 8][2 * t];
            ah[mi][2] = *(const uint32_t*)&As_h[buf][r][2 * t + 8];
            ah[mi][3] = *(const uint32_t*)&As_h[buf][r + 8][2 * t + 8];
            al[mi][0] = *(const uint32_t*)&As_l[buf][r][2 * t];
            al[mi][1] = *(const uint32_t*)&As_l[buf][r + 8][2 * t];
            al[mi][2] = *(const uint32_t*)&As_l[buf][r][2 * t + 8];
            al[mi][3] = *(const uint32_t*)&As_l[buf][r + 8][2 * t + 8];
        }
#pragma unroll
        for (int ni = 0; ni < 8; ni++) {
            int n = wn * 64 + ni * 8 + g;
            uint32_t bh0 = *(const uint32_t*)&Bt_h[buf][n][2 * t];
            uint32_t bh1 = *(const uint32_t*)&Bt_h[buf][n][2 * t + 8];
            uint32_t bl0 = *(const uint32_t*)&Bt_l[buf][n][2 * t];
            uint32_t bl1 = *(const uint32_t*)&Bt_l[buf][n][2 * t + 8];
#pragma unroll
            for (int mi = 0; mi < 2; mi++) {
                mma_bf16(c[mi][ni], ah[mi], bh0, bh1);
                mma_bf16(c[mi][ni], ah[mi], bl0, bl1);
                mma_bf16(c[mi][ni], al[mi], bh0, bh1);
            }
        }

        if (k < 7) {
            bf8 hi, lo;
#pragma unroll
            for (int q = 0; q < 8; q++) {
                __nv_bfloat16 h = __float2bfloat16_rn(vv[q]);
                hi.v[q] = h;
                lo.v[q] = __float2bfloat16_rn(vv[q] - __bfloat162float(h));
            }
            *(uint4*)&As_h[nbuf][a_row][a_colq] = *(const uint4*)&hi;
            *(uint4*)&As_l[nbuf][a_row][a_colq] = *(const uint4*)&lo;
            asm volatile("cp.async.wait_group 0;");
            __syncthreads();
        }
    }

    // epilogue
#pragma unroll
    for (int ni = 0; ni < 8; ni++) {
        int col = wn * 64 + ni * 8 + 2 * t;
        float b0 = bias ? bias[col] : 0.f;
        float b1 = bias ? bias[col + 1] : 0.f;
#pragma unroll
        for (int mi = 0; mi < 2; mi++) {
            int row = m0 + wm * 32 + mi * 16 + g;
            float2 o0 = make_float2(c[mi][ni][0] + b0, c[mi][ni][1] + b1);
            float2 o1 = make_float2(c[mi][ni][2] + b0, c[mi][ni][3] + b1);
            *(float2*)(C + (size_t)row * 128 + col) = o0;
            *(float2*)(C + (size_t)(row + 8) * 128 + col) = o1;
        }
    }
}

// ---------------------------------------------------------------- aggregations
// EdgeConv: h_b[d] = softplus( deg>0 ? P[d] + max_in Q[src] : 0 ). Warp/node.
__global__ void edgeconv_agg(int step1, const int* __restrict__ remap,
                             float* __restrict__ outExt, int N_) {
    int w = (blockIdx.x * blockDim.x + threadIdx.x) >> 5;
    if (w >= N_) return;
    int lane = threadIdx.x & 31;
    const float* P = step1 ? g_P20 : g_X;
    const float* Q = step1 ? g_Q20 : g_Y;
    int lo = g_rowptr[w], hi = g_rowptr[w + 1];
    float4 r;
    if (lo == hi) {
        r = make_float4(C0, C0, C0, C0);
    } else {
        float4 m = make_float4(-FLT_MAX, -FLT_MAX, -FLT_MAX, -FLT_MAX);
        for (int i = lo; i < hi; i++) {
            int s = g_csr[i].x;
            int qs = step1 ? remap[s] : s;
            float4 q = *(const float4*)(Q + (size_t)qs * 128 + lane * 4);
            m.x = fmaxf(m.x, q.x); m.y = fmaxf(m.y, q.y);
            m.z = fmaxf(m.z, q.z); m.w = fmaxf(m.w, q.w);
        }
        int pd = step1 ? remap[w] : w;
        float4 p = *(const float4*)(P + (size_t)pd * 128 + lane * 4);
        r = make_float4(sp(p.x + m.x), sp(p.y + m.y), sp(p.z + m.z), sp(p.w + m.w));
    }
    float* o = outExt ? outExt : g_hb;
    *(float4*)(o + (size_t)w * 128 + lane * 4) = r;
}

// GeneralConv: h_a[d] = softplus( sum_in (A[src] + (e<N ? Bv[e] : Cc)) + h_a[d] )
__global__ void genconv_agg(float* __restrict__ outExt, int N_) {
    int w = (blockIdx.x * blockDim.x + threadIdx.x) >> 5;
    if (w >= N_) return;
    int lane = threadIdx.x & 31;
    int lo = g_rowptr[w], hi = g_rowptr[w + 1];
    float4 acc = make_float4(0.f, 0.f, 0.f, 0.f);
    for (int i = lo; i < hi; i++) {
        int2 se = g_csr[i];
        float4 a = *(const float4*)(g_X + (size_t)se.x * 128 + lane * 4);
        const float* Bp = (se.y < N_) ? (g_Y + (size_t)se.y * 128) : g_Cc;
        float4 b = *(const float4*)(Bp + lane * 4);
        acc.x += a.x + b.x; acc.y += a.y + b.y;
        acc.z += a.z + b.z; acc.w += a.w + b.w;
    }
    float4 h = *(const float4*)(g_ha + (size_t)w * 128 + lane * 4);
    float4 r = make_float4(sp(acc.x + h.x), sp(acc.y + h.y), sp(acc.z + h.z), sp(acc.w + h.w));
    float* o = outExt ? outExt : g_ha;
    *(float4*)(o + (size_t)w * 128 + lane * 4) = r;
}

__global__ void k_fill_tail(float* __restrict__ dst4, size_t count4) {
    size_t i = (size_t)blockIdx.x * blockDim.x + threadIdx.x;
    if (i < count4) ((float4*)dst4)[i] = make_float4(C0, C0, C0, C0);
}

// ---------------------------------------------------------------- pool + MLP
__device__ __forceinline__ int lbound(const int* a, int n, int key) {
    int lo = 0, hi = n;
    while (lo < hi) {
        int mid = (lo + hi) >> 1;
        if (a[mid] < key) lo = mid + 1; else hi = mid;
    }
    return lo;
}
__global__ void k_pool(const int* __restrict__ batch, const float* __restrict__ HA, int N_) {
    int g = blockIdx.x, j = threadIdx.x;
    int lo = lbound(batch, N_, g), hi = lbound(batch, N_, g + 1);
    float acc = 0.f;
    for (int n = lo; n < hi; n++) acc += HA[(size_t)n * 128 + j];
    g_pooled[g * 128 + j] = acc;
}
__global__ void k_readout(const float* __restrict__ Wr1, const float* __restrict__ br1,
                          const float* __restrict__ Wr2, const float* __restrict__ br2,
                          const float* __restrict__ Wr3, const float* __restrict__ br3,
                          float* __restrict__ out) {
    int g = blockIdx.x, j = threadIdx.x;  // 64 threads
    __shared__ float p[128];
    __shared__ float h[64];
    __shared__ float part[2];
    p[j] = g_pooled[g * 128 + j];
    p[j + 64] = g_pooled[g * 128 + 64 + j];
    __syncthreads();
    float s = br1[j];
    for (int k = 0; k < 128; k++) s = fmaf(p[k], Wr1[k * 64 + j], s);
    h[j] = sp(s);
    __syncthreads();
    float s2 = br2[j];
    for (int k = 0; k < 64; k++) s2 = fmaf(h[k], Wr2[k * 64 + j], s2);
    float v = sp(s2) * Wr3[j];
#pragma unroll
    for (int o = 16; o; o >>= 1) v += __shfl_down_sync(0xffffffffu, v, o);
    if ((j & 31) == 0) part[j >> 5] = v;
    __syncthreads();
    if (j == 0) out[g] = part[0] + part[1] + br3[0];
}

// ---------------------------------------------------------------- launch
extern "C" void kernel_launch(void* const* d_in, const int* in_sizes, int n_in,
                              void* d_out, int out_size) {
    const int* x_ids = (const int*)d_in[0];
    const int* eaid  = (const int*)d_in[1];
    const int* eidx  = (const int*)d_in[2];
    const int* batch = (const int*)d_in[3];
    const float* emb_atom = (const float*)d_in[4];
    const float* emb_bond = (const float*)d_in[5];
    const float* Wb  = (const float*)d_in[6];
    const float* bb  = (const float*)d_in[7];
    const float* Wm  = (const float*)d_in[8];
    const float* bm  = (const float*)d_in[9];
    const float* We  = (const float*)d_in[10];
    const float* be  = (const float*)d_in[11];
    const float* Wr1 = (const float*)d_in[12];
    const float* br1 = (const float*)d_in[13];
    const float* Wr2 = (const float*)d_in[14];
    const float* br2 = (const float*)d_in[15];
    const float* Wr3 = (const float*)d_in[16];
    const float* br3 = (const float*)d_in[17];
    const int N = in_sizes[0];
    const int E = in_sizes[1];
    const int G = out_size - 128 * (N + E);   // 4096
    const int* srcp = eidx;
    const int* dstp = eidx + E;
    float* out = (float*)d_out;
    float* out_ha = out + G;
    float* out_hb = out_ha + (size_t)N * 128;

    const int nb = (N + 1023) / 1024;
    const int Npad = ((N + 127) / 128) * 128;
    const int gemm_grid = Npad / 128;
    const int agg_grid = (N + 7) / 8;

    // hoisted init + A1 GEMM (deps satisfied) so ncu's captured launch (#3)
    // is the hot GEMM kernel
    k_init_ha<<<(N * 128 + 255) / 256, 256>>>(x_ids, emb_atom, N);   // idx0
    k_splitT<<<64, 256>>>(Wm, 0);                                     // idx1
    k_splitT<<<64, 256>>>(We, 1);                                     // idx2
    gemm_bf16<<<gemm_grid, 256>>>(0, nullptr, 0, bm, 2);              // idx3: A1 = h_a0@Wm+bm -> X

    // CSR by dst
    k_zero_deg<<<(N + 255) / 256, 256>>>(N);
    k_hist<<<(E + 255) / 256, 256>>>(dstp, E);
    k_scan1<<<nb, 1024>>>(N);
    k_scan2<<<1, 1024>>>(nb);
    k_scan3<<<(N + 255) / 256, 256>>>(N, E);
    k_fill_csr<<<(E + 255) / 256, 256>>>(srcp, dstp, E);

    // remaining prep
    k_prep_wp<<<64, 256>>>(Wb);
    k_splitT_wb<<<64, 256>>>(Wb);
    k_prep_pq20<<<20, 128>>>(emb_bond, Wb, bb);
    k_prep_c<<<1, 128>>>(We, be);

    // ---- step 1 ----
    edgeconv_agg<<<agg_grid, 256>>>(1, eaid, nullptr, N);            // h_b1 -> g_hb
    gemm_bf16<<<gemm_grid, 256>>>(1, nullptr, 1, be, 3);             // Bv1 = h_b1@We+be -> Y
    genconv_agg<<<agg_grid, 256>>>(nullptr, N);                      // h_a1 -> g_ha (in place)

    // ---- step 2 ----
    gemm_bf16<<<gemm_grid, 256>>>(1, nullptr, 2, bb, 2);             // P2 = h_b1@WP+bb -> X
    gemm_bf16<<<gemm_grid, 256>>>(1, nullptr, 3, nullptr, 3);        // Q2 = h_b1@W2 -> Y
    edgeconv_agg<<<agg_grid, 256>>>(0, nullptr, out_hb, N);          // h_b2 -> out_hb rows < N
    {
        size_t count4 = ((size_t)(E - N) * 128) / 4;                 // rows >= N are softplus(0)
        k_fill_tail<<<(unsigned)((count4 + 255) / 256), 256>>>(out_hb + (size_t)N * 128, count4);
    }
    gemm_bf16<<<gemm_grid, 256>>>(0, nullptr, 0, bm, 2);             // A2  = h_a1@Wm+bm -> X
    gemm_bf16<<<gemm_grid, 256>>>(4, out_hb, 1, be, 3);              // Bv2 = h_b2@We+be -> Y
    genconv_agg<<<agg_grid, 256>>>(out_ha, N);                       // h_a2 -> out_ha

    // ---- pool + readout ----
    k_pool<<<G, 128>>>(batch, out_ha, N);
    k_readout<<<G, 64>>>(Wr1, br1, Wr2, br2, Wr3, br3, out);
}